// round 1
// baseline (speedup 1.0000x reference)
#include <cuda_runtime.h>
#include <math.h>

// Problem dims
#define NB 16
#define CI 128
#define CO 256
#define XH 128
#define XW 128
#define KK 9           // 3x3
#define KTOT (CI*KK)   // 1152
#define NXTOT (NB*CI*XH*XW)   // 33554432

// Scratch (device globals -- no allocation allowed)
__device__ float    d_xq[NXTOT];          // quantized x (exact integers in fp32)
__device__ float    d_wqt[KTOT*CO];       // quantized W, transposed: [ci*9+k][oc]
__device__ float    d_fw[CO];
__device__ unsigned d_xmax_bits;
__device__ float    d_fx;

// ---------------- init ----------------
__global__ void k_init() { d_xmax_bits = 0u; }

// ---------------- global abs-max of x ----------------
__global__ void k_xmax(const float* __restrict__ x, int n4) {
    const float4* x4 = (const float4*)x;
    float m = 0.f;
    for (int i = blockIdx.x * blockDim.x + threadIdx.x; i < n4;
         i += gridDim.x * blockDim.x) {
        float4 v = x4[i];
        m = fmaxf(m, fmaxf(fmaxf(fabsf(v.x), fabsf(v.y)),
                           fmaxf(fabsf(v.z), fabsf(v.w))));
    }
    __shared__ float sm[256];
    sm[threadIdx.x] = m;
    __syncthreads();
    for (int s = 128; s > 0; s >>= 1) {
        if (threadIdx.x < s) sm[threadIdx.x] = fmaxf(sm[threadIdx.x], sm[threadIdx.x + s]);
        __syncthreads();
    }
    if (threadIdx.x == 0)
        atomicMax(&d_xmax_bits, __float_as_uint(sm[0]));  // all vals >= 0: bit order == float order
}

// ---------------- fx = f32(4096*sqrt(1/24) - 0.5) / x_max ----------------
__global__ void k_fx() {
    float xmax = __uint_as_float(d_xmax_bits);
    float c = (float)(4096.0 * sqrt(48.0 / 1152.0) - 0.5);
    d_fx = (xmax > 0.f) ? (c / xmax) : 1.0f;
}

// ---------------- xq = rint(fx * x)  (round-half-even == jnp.round) ----------------
__global__ void k_qx(const float* __restrict__ x, int n4) {
    const float fx = d_fx;
    const float4* x4 = (const float4*)x;
    float4* o4 = (float4*)d_xq;
    for (int i = blockIdx.x * blockDim.x + threadIdx.x; i < n4;
         i += gridDim.x * blockDim.x) {
        float4 v = x4[i];
        float4 r;
        r.x = rintf(fx * v.x);
        r.y = rintf(fx * v.y);
        r.z = rintf(fx * v.z);
        r.w = rintf(fx * v.w);
        o4[i] = r;
    }
}

// ---------------- per-out-channel: w_sum, fw, wq (transposed store) ----------------
__global__ void k_qw(const float* __restrict__ W) {
    const int o = blockIdx.x;      // 256 blocks
    const int t = threadIdx.x;     // 128 threads, one per ci
    const float* wo = W + o * KTOT;
    float vals[KK];
    float s = 0.f;
#pragma unroll
    for (int k = 0; k < KK; ++k) {
        vals[k] = wo[t * KK + k];
        s += fabsf(vals[k]);
    }
    __shared__ float sm[128];
    __shared__ float sfw;
    sm[t] = s;
    __syncthreads();
    for (int st = 64; st > 0; st >>= 1) {
        if (t < st) sm[t] += sm[t + st];
        __syncthreads();
    }
    if (t == 0) {
        float ws = sm[0];
        if (ws == 0.f) ws = 1.f;
        // factor/sf - sqrt(N/12)*5 = 4096*sqrt(24) - 5*sqrt(96), computed f64, cast f32
        float num = (float)(4096.0 * sqrt(24.0) - 5.0 * sqrt(96.0));
        float fw = num / ws;
        d_fw[o] = fw;
        sfw = fw;
    }
    __syncthreads();
    float fw = sfw;
#pragma unroll
    for (int k = 0; k < KK; ++k)
        d_wqt[(t * KK + k) * CO + o] = rintf(vals[k] * fw);
}

// ---------------- conv: one (n, h) row x 64 output channels per block ----------------
// Thread map: wlane = tid&15, ocg = tid>>4.  Output w = wlane + 16*wi (wi 0..7),
// oc = oc0 + ocg*4 + oi (oi 0..3).  Strided-w makes all smem x-loads
// conflict-free (16 consecutive addrs + 2-way broadcast).
__global__ void __launch_bounds__(256)
conv_kernel(const float* __restrict__ bias, float* __restrict__ out) {
    __shared__ float sx[3][132];     // rows h-1..h+1, cols w=-1..128 (index = w+1)
    __shared__ float swt[KK][64];    // [k][ocl]

    const int h   = blockIdx.x;
    const int oc0 = blockIdx.y * 64;
    const int n   = blockIdx.z;
    const int tid = threadIdx.x;
    const int wlane = tid & 15;
    const int ocg   = tid >> 4;

    float acc[4][8];
#pragma unroll
    for (int oi = 0; oi < 4; ++oi)
#pragma unroll
        for (int wi = 0; wi < 8; ++wi) acc[oi][wi] = 0.f;

    const float* xn = d_xq + (size_t)n * CI * XH * XW;

    for (int ci = 0; ci < CI; ++ci) {
        // stage x halo rows: 3 x 130
        const float* xp = xn + (size_t)ci * XH * XW;
        for (int i = tid; i < 390; i += 256) {
            int r = i / 130;
            int c = i - r * 130;
            int gh = h - 1 + r;
            int gw = c - 1;
            float v = 0.f;
            if ((unsigned)gh < XH && (unsigned)gw < XW) v = xp[gh * XW + gw];
            sx[r][c] = v;
        }
        // stage weights for this ci: swt[k][ocl] (coalesced from transposed layout)
        {
            const float* wp = d_wqt + (size_t)ci * KK * CO + oc0;
            for (int i = tid; i < 576; i += 256) {
                int k = i >> 6, ocl = i & 63;
                swt[k][ocl] = wp[k * CO + ocl];
            }
        }
        __syncthreads();

#pragma unroll
        for (int kh = 0; kh < 3; ++kh) {
            float4 w0 = *(const float4*)&swt[kh * 3 + 0][ocg * 4];
            float4 w1 = *(const float4*)&swt[kh * 3 + 1][ocg * 4];
            float4 w2 = *(const float4*)&swt[kh * 3 + 2][ocg * 4];
#pragma unroll
            for (int wi = 0; wi < 8; ++wi) {
                float x0 = sx[kh][wlane + 16 * wi + 0];
                float x1 = sx[kh][wlane + 16 * wi + 1];
                float x2 = sx[kh][wlane + 16 * wi + 2];
                acc[0][wi] += x0 * w0.x + x1 * w1.x + x2 * w2.x;
                acc[1][wi] += x0 * w0.y + x1 * w1.y + x2 * w2.y;
                acc[2][wi] += x0 * w0.z + x1 * w1.z + x2 * w2.z;
                acc[3][wi] += x0 * w0.w + x1 * w1.w + x2 * w2.w;
            }
        }
        __syncthreads();
    }

    // epilogue: dequant + bias + relu
    const float fx = d_fx;
#pragma unroll
    for (int oi = 0; oi < 4; ++oi) {
        int oc = oc0 + ocg * 4 + oi;
        float inv = 1.0f / (fx * d_fw[oc]);
        float bv  = bias[oc];
        float* op = out + (((size_t)n * CO + oc) * XH + h) * XW;
#pragma unroll
        for (int wi = 0; wi < 8; ++wi) {
            int w = wlane + 16 * wi;
            float v = acc[oi][wi] * inv + bv;
            op[w] = v > 0.f ? v : 0.f;
        }
    }
}

extern "C" void kernel_launch(void* const* d_in, const int* in_sizes, int n_in,
                              void* d_out, int out_size) {
    const float* x = (const float*)d_in[0];   // [16,128,128,128]
    const float* W = (const float*)d_in[1];   // [256,128,3,3]
    const float* b = (const float*)d_in[2];   // [256]
    float* out = (float*)d_out;               // [16,256,128,128]

    k_init<<<1, 1>>>();
    k_xmax<<<1024, 256>>>(x, NXTOT / 4);
    k_fx<<<1, 1>>>();
    k_qx<<<2048, 256>>>(x, NXTOT / 4);
    k_qw<<<CO, 128>>>(W);

    dim3 grid(XH, CO / 64, NB);
    conv_kernel<<<grid, 256>>>(b, out);
}

// round 9
// speedup vs baseline: 9.2143x; 9.2143x over previous
#include <cuda_runtime.h>
#include <cuda_fp16.h>
#include <math.h>
#include <stdint.h>

#define NB 16
#define CI 128
#define CO 256
#define XH 128
#define XW 128
#define HP 130           // padded spatial dim
#define NXTOT (NB*CI*XH*XW)

// -------- device scratch (no allocation allowed) --------
__device__ __align__(16) __half d_xqh[(size_t)NB*HP*HP*CI]; // NHWC fp16, zero halo
__device__ __align__(16) __half d_wqh[4*9*CO*32];           // [cichunk][tap][oc][ci_in]
__device__ float    d_fw[CO];
__device__ unsigned d_xmax_bits;
__device__ float    d_fx;

// -------- PTX helpers --------
__device__ __forceinline__ void cpa16(uint32_t dst, const void* src) {
    asm volatile("cp.async.cg.shared.global [%0], [%1], 16;\n" :: "r"(dst), "l"(src));
}
__device__ __forceinline__ void cp_commit() {
    asm volatile("cp.async.commit_group;\n");
}
template<int N> __device__ __forceinline__ void cp_wait() {
    asm volatile("cp.async.wait_group %0;\n" :: "n"(N));
}
__device__ __forceinline__ uint32_t lds32(uint32_t a) {
    uint32_t v; asm volatile("ld.shared.b32 %0, [%1];\n" : "=r"(v) : "r"(a)); return v;
}
__device__ __forceinline__ void ldsm4(uint32_t* r, uint32_t a) {
    asm volatile("ldmatrix.sync.aligned.m8n8.x4.shared.b16 {%0,%1,%2,%3}, [%4];\n"
                 : "=r"(r[0]), "=r"(r[1]), "=r"(r[2]), "=r"(r[3]) : "r"(a));
}
__device__ __forceinline__ void mma16816(float* c, const uint32_t* a, uint32_t b0, uint32_t b1) {
    asm volatile("mma.sync.aligned.m16n8k16.row.col.f32.f16.f16.f32 "
                 "{%0,%1,%2,%3}, {%4,%5,%6,%7}, {%8,%9}, {%0,%1,%2,%3};\n"
                 : "+f"(c[0]), "+f"(c[1]), "+f"(c[2]), "+f"(c[3])
                 : "r"(a[0]), "r"(a[1]), "r"(a[2]), "r"(a[3]), "r"(b0), "r"(b1));
}

// -------- small kernels --------
__global__ void k_init() { d_xmax_bits = 0u; }

// zero ONLY the halo of d_xqh (interior is fully rewritten by k_qxh each call).
// grid (16 n, 4 region), 256 thr. regions: 0/1 = full rows ph=0,129; 2/3 = cols pw=0,129.
__global__ void k_zero_halo() {
    const int n = blockIdx.x, reg = blockIdx.y, tid = threadIdx.x;
    __half* base = d_xqh + (size_t)n * HP * HP * CI;
    uint4 z; z.x = z.y = z.z = z.w = 0u;
    if (reg < 2) {
        uint4* p = (uint4*)(base + (size_t)(reg ? (HP - 1) : 0) * HP * CI);
        for (int i = tid; i < HP * CI / 8; i += blockDim.x) p[i] = z;   // 2080 uint4
    } else {
        const int pw = (reg == 2) ? 0 : (HP - 1);
        for (int i = tid; i < 128 * (CI / 8); i += blockDim.x) {        // 2048 uint4
            int ph = 1 + (i >> 4), seg = i & 15;
            ((uint4*)(base + ((size_t)ph * HP + pw) * CI))[seg] = z;
        }
    }
}

__global__ void k_xmax(const float* __restrict__ x, int n4) {
    const float4* x4 = (const float4*)x;
    float m = 0.f;
    for (int i = blockIdx.x*blockDim.x + threadIdx.x; i < n4; i += gridDim.x*blockDim.x) {
        float4 v = x4[i];
        m = fmaxf(m, fmaxf(fmaxf(fabsf(v.x), fabsf(v.y)), fmaxf(fabsf(v.z), fabsf(v.w))));
    }
    __shared__ float sm[256];
    sm[threadIdx.x] = m; __syncthreads();
    for (int s = 128; s > 0; s >>= 1) {
        if (threadIdx.x < s) sm[threadIdx.x] = fmaxf(sm[threadIdx.x], sm[threadIdx.x+s]);
        __syncthreads();
    }
    if (threadIdx.x == 0) atomicMax(&d_xmax_bits, __float_as_uint(sm[0]));
}

__global__ void k_fx() {
    float xmax = __uint_as_float(d_xmax_bits);
    float c = (float)(4096.0 * sqrt(48.0 / 1152.0) - 0.5);
    d_fx = (xmax > 0.f) ? (c / xmax) : 1.0f;
}

// quantize + NCHW->padded-NHWC(fp16) transpose. grid (128 h, 4 cichunk, 16 n), 256 thr
__global__ void k_qxh(const float* __restrict__ x) {
    __shared__ float sm[32][133];
    const int h = blockIdx.x, cc = blockIdx.y, n = blockIdx.z;
    const int tid = threadIdx.x;
    const float fx = d_fx;
    const int r  = tid >> 3;
    const int cb = (tid & 7) * 16;
    const float* rp = x + (((size_t)(n*CI + cc*32 + r))*XH + h)*XW;
#pragma unroll
    for (int j = 0; j < 4; ++j) {
        float4 v = *(const float4*)(rp + cb + j*4);
        sm[r][cb + j*4 + 0] = rintf(fx*v.x);
        sm[r][cb + j*4 + 1] = rintf(fx*v.y);
        sm[r][cb + j*4 + 2] = rintf(fx*v.z);
        sm[r][cb + j*4 + 3] = rintf(fx*v.w);
    }
    __syncthreads();
    const int ci2 = (tid & 15) * 2;
    const int pb  = tid >> 4;
    __half* dst = d_xqh + (((size_t)(n*HP + h + 1))*HP + 1)*CI + cc*32 + ci2;
#pragma unroll
    for (int it = 0; it < 8; ++it) {
        int p = pb + it*16;
        __half2 hv = __floats2half2_rn(sm[ci2][p], sm[ci2+1][p]);
        *(__half2*)(dst + (size_t)p*CI) = hv;
    }
}

// per-oc: w_sum -> fw -> wq fp16 in [cichunk][tap][oc][ci_in] layout. 256 blocks x 128 thr
__global__ void k_qw(const float* __restrict__ W) {
    const int o = blockIdx.x, t = threadIdx.x;
    const float* wo = W + o*CI*9;
    float vals[9]; float s = 0.f;
#pragma unroll
    for (int k = 0; k < 9; ++k) { vals[k] = wo[t*9 + k]; s += fabsf(vals[k]); }
    __shared__ float sm[128]; __shared__ float sfw;
    sm[t] = s; __syncthreads();
    for (int st = 64; st > 0; st >>= 1) {
        if (t < st) sm[t] += sm[t+st];
        __syncthreads();
    }
    if (t == 0) {
        float ws = sm[0]; if (ws == 0.f) ws = 1.f;
        float num = (float)(4096.0*sqrt(24.0) - 5.0*sqrt(96.0));
        float fw = num / ws;
        d_fw[o] = fw; sfw = fw;
    }
    __syncthreads();
    float fw = sfw;
    const int chunk = t >> 5, cin = t & 31;
#pragma unroll
    for (int k = 0; k < 9; ++k)
        d_wqh[(((size_t)(chunk*9 + k))*CO + o)*32 + cin] = __float2half_rn(rintf(vals[k]*fw));
}

// -------- conv: implicit GEMM with mma.sync --------
// CTA: 256 pixels (2 h-rows x 128 w) x 128 oc. 512 threads, 16 warps (warp 64x32).
// smem: A = 2 x (520 rows x 40 half = 80B pitch) = 2x41600; B = 3 x (384 x 80B) = 3x30720.
#define SA_BYTES 41600
#define SB_BYTES 30720
#define SMEM_TOTAL (2*SA_BYTES + 3*SB_BYTES)   // 175360

__device__ __forceinline__ void issue_stage(int s, int n, int h0, int oc0,
                                            uint32_t sA0, uint32_t sB0, int tid) {
    const int chunk = s / 3, g = s - chunk*3;
    {
        const uint32_t bBuf = sB0 + (uint32_t)(s % 3) * SB_BYTES;
        const __half* wb = d_wqh + ((size_t)((chunk*9 + g*3)*CO + oc0)) * 32;
#pragma unroll
        for (int j = 0; j < 3; ++j) {            // 1536 segs / 512 thr
            int i = tid + j*512;
            int r = i >> 2, seg = i & 3;
            int kt = r >> 7, ocl = r & 127;
            cpa16(bBuf + (uint32_t)r*80 + seg*16, wb + ((size_t)(kt*CO + ocl))*32 + seg*8);
        }
    }
    if (g == 0) {
        const uint32_t aBuf = sA0 + (uint32_t)(chunk & 1) * SA_BYTES;
        const __half* xb = d_xqh + ((size_t)(n*HP + h0))*HP*CI + chunk*32;
        for (int i = tid; i < 2080; i += 512) {  // 520 rows x 4 segs
            int r = i >> 2, seg = i & 3;
            cpa16(aBuf + (uint32_t)r*80 + seg*16, xb + (size_t)r*CI + seg*8);
        }
    }
}

__global__ void __launch_bounds__(512, 1)
conv_kernel(const float* __restrict__ bias, float* __restrict__ out) {
    extern __shared__ __align__(16) char smem[];
    const uint32_t sA0 = (uint32_t)__cvta_generic_to_shared(smem);
    const uint32_t sB0 = sA0 + 2*SA_BYTES;

    const int tid  = threadIdx.x;
    const int lane = tid & 31, wid = tid >> 5;
    const int warp_m = wid & 3, warp_n = wid >> 2;
    const int gid = lane >> 2, tig = lane & 3;
    const int hr  = warp_m >> 1;
    const int wm  = (warp_m & 1) * 64;
    const int lrow = lane & 15, lseg = lane >> 4;

    const int h0  = blockIdx.x * 2;
    const int oc0 = blockIdx.y * 128;
    const int n   = blockIdx.z;

    float acc[4][4][4];
#pragma unroll
    for (int mt = 0; mt < 4; ++mt)
#pragma unroll
        for (int nt = 0; nt < 4; ++nt)
#pragma unroll
            for (int q = 0; q < 4; ++q) acc[mt][nt][q] = 0.f;

    issue_stage(0, n, h0, oc0, sA0, sB0, tid); cp_commit();
    issue_stage(1, n, h0, oc0, sA0, sB0, tid); cp_commit();

    for (int s = 0; s < 12; ++s) {
        if (s < 10) cp_wait<1>(); else cp_wait<0>();
        __syncthreads();
        if (s < 10) { issue_stage(s + 2, n, h0, oc0, sA0, sB0, tid); cp_commit(); }

        const int chunk = s / 3, g = s - chunk*3;
        const uint32_t aBuf = sA0 + (uint32_t)(chunk & 1) * SA_BYTES;
        const uint32_t bBuf = sB0 + (uint32_t)(s % 3) * SB_BYTES;
        const int arowbase = (hr + g)*HP + wm + lrow;

#pragma unroll
        for (int kt = 0; kt < 3; ++kt) {        // dw = kt
#pragma unroll
            for (int k2 = 0; k2 < 2; ++k2) {    // two k16 halves of 32-ci chunk
                uint32_t b[4][2];
#pragma unroll
                for (int nt = 0; nt < 4; ++nt) {
                    uint32_t ba = bBuf + (uint32_t)(kt*128 + warp_n*32 + nt*8 + gid)*80
                                + tig*4 + k2*32;
                    b[nt][0] = lds32(ba);
                    b[nt][1] = lds32(ba + 16);
                }
#pragma unroll
                for (int mt = 0; mt < 4; ++mt) {
                    uint32_t aa = aBuf + (uint32_t)(arowbase + mt*16 + kt)*80
                                + lseg*16 + k2*32;
                    uint32_t a[4]; ldsm4(a, aa);
#pragma unroll
                    for (int nt = 0; nt < 4; ++nt)
                        mma16816(acc[mt][nt], a, b[nt][0], b[nt][1]);
                }
            }
        }
    }

    // epilogue: dequant + bias + relu, direct stores
    const float fx = d_fx;
    const int ho = h0 + hr;
#pragma unroll
    for (int nt = 0; nt < 4; ++nt) {
        const int oc = oc0 + warp_n*32 + nt*8 + tig*2;
        const float i0 = 1.0f / (fx * d_fw[oc]);
        const float i1 = 1.0f / (fx * d_fw[oc+1]);
        const float b0 = bias[oc], b1 = bias[oc+1];
        float* p0 = out + (((size_t)(n*CO + oc))*XH + ho)*XW;
        float* p1 = p0 + (size_t)XH*XW;
#pragma unroll
        for (int mt = 0; mt < 4; ++mt) {
            const int wo = wm + mt*16 + gid;
            float v;
            v = acc[mt][nt][0]*i0 + b0; p0[wo]     = v > 0.f ? v : 0.f;
            v = acc[mt][nt][1]*i1 + b1; p1[wo]     = v > 0.f ? v : 0.f;
            v = acc[mt][nt][2]*i0 + b0; p0[wo + 8] = v > 0.f ? v : 0.f;
            v = acc[mt][nt][3]*i1 + b1; p1[wo + 8] = v > 0.f ? v : 0.f;
        }
    }
}

extern "C" void kernel_launch(void* const* d_in, const int* in_sizes, int n_in,
                              void* d_out, int out_size) {
    const float* x = (const float*)d_in[0];   // [16,128,128,128]
    const float* W = (const float*)d_in[1];   // [256,128,3,3]
    const float* b = (const float*)d_in[2];   // [256]
    float* out = (float*)d_out;               // [16,256,128,128] f32

    k_init<<<1, 1>>>();
    k_zero_halo<<<dim3(NB, 4), 256>>>();
    k_xmax<<<1024, 256>>>(x, NXTOT / 4);
    k_fx<<<1, 1>>>();
    k_qxh<<<dim3(XH, 4, NB), 256>>>(x);
    k_qw<<<CO, 128>>>(W);

    cudaFuncSetAttribute(conv_kernel, cudaFuncAttributeMaxDynamicSharedMemorySize, SMEM_TOTAL);
    conv_kernel<<<dim3(XH/2, CO/128, NB), 512, SMEM_TOTAL>>>(b, out);
}